// round 9
// baseline (speedup 1.0000x reference)
#include <cuda_runtime.h>
#include <math.h>

#define BB 4
#define NN 8192
#define KNB 9
#define CH 7
#define BNK (BB*NN*KNB)
#define TILE 1024
#define BN_EPS 1e-5f
#define NEGINF (-3.4e38f)

// scratch (allocation-free): SoA feature buffer [channel][bnk] and BN accumulators
__device__ float g_feat[CH * BNK];
__device__ float g_acc[28];   // [0:7) sum1, [7:14) sumsq1, [14:21) sum2, [21:28) sumsq2

__global__ void k_zero() {
    int t = threadIdx.x;
    if (t < 28) g_acc[t] = 0.f;
}

// Parallel-select sorted insert (desc). Insert position = #{dst[k] >= d}:
// all predicates independent, outputs read only pre-insert state -> depth 2.
// Strict > keeps lower index on ties (ascending-j scan), matching jax.lax.top_k.
// d <= dst[9] (incl. NEGINF) is a guaranteed no-op.
__device__ __forceinline__ void ins10(float d, int j, float dst[10], int idx[10]) {
    bool p[10];
#pragma unroll
    for (int k = 0; k < 10; k++) p[k] = d > dst[k];
#pragma unroll
    for (int k = 9; k >= 1; k--) {
        dst[k] = p[k] ? (p[k-1] ? dst[k-1] : d) : dst[k];
        idx[k] = p[k] ? (p[k-1] ? idx[k-1] : j) : idx[k];
    }
    dst[0] = p[0] ? d : dst[0];
    idx[0] = p[0] ? j : idx[0];
}

// ---------------------------------------------------------------------------
// K1: brute-force top-10 (dist = 2*x.y - |x|^2 - |y|^2, desc) + umbrella
//     geometry + first 7x7 linear, accumulate BN1 stats
//     128-thread CTAs -> 256 CTAs -> all 148 SMs busy
// ---------------------------------------------------------------------------
__global__ __launch_bounds__(128) void k_knn(const float* __restrict__ x,
                                             const float* __restrict__ w1) {
    __shared__ float4 tile[TILE];
    __shared__ float s_w1[49];
    __shared__ float s_acc[14];

    const int tid = threadIdx.x;
    const int b = blockIdx.x >> 6;                 // 64 blocks per batch
    const int n = (blockIdx.x & 63) * 128 + tid;
    const float* xb = x + (size_t)b * NN * 3;

    if (tid < 49) s_w1[tid] = w1[tid];
    if (tid < 14) s_acc[tid] = 0.f;

    const float x0 = xb[n*3+0], x1 = xb[n*3+1], x2 = xb[n*3+2];
    const float xsqi = fmaf(x2, x2, fmaf(x1, x1, x0*x0));

    float dst[10]; int idx[10];
#pragma unroll
    for (int k = 0; k < 10; k++) { dst[k] = NEGINF; idx[k] = -1; }
    float thr = NEGINF;

    for (int base = 0; base < NN; base += TILE) {
        __syncthreads();
        for (int j = tid; j < TILE; j += 128) {
            float a  = xb[(base+j)*3+0];
            float c1 = xb[(base+j)*3+1];
            float c2 = xb[(base+j)*3+2];
            tile[j] = make_float4(a, c1, c2, fmaf(c2, c2, fmaf(c1, c1, a*a)));
        }
        __syncthreads();
        for (int j0 = 0; j0 < TILE; j0 += 8) {
            float dv[8];
#pragma unroll
            for (int u = 0; u < 8; u++) {
                float4 s = tile[j0 + u];            // uniform addr -> smem broadcast
                float t = x0 * s.x;
                t = fmaf(x1, s.y, t);
                t = fmaf(x2, s.z, t);
                dv[u] = fmaf(2.0f, t, -xsqi) - s.w; // same rounding as ref
            }
            // 8-wide pre-screen: one vote/branch per 8 candidates
            float m01 = fmaxf(dv[0], dv[1]), m23 = fmaxf(dv[2], dv[3]);
            float m45 = fmaxf(dv[4], dv[5]), m67 = fmaxf(dv[6], dv[7]);
            float m = fmaxf(fmaxf(m01, m23), fmaxf(m45, m67));
            if (__any_sync(0xffffffffu, m > thr)) {
                // stale thr for the whole block: decouples the 8 steps
                // (below-live-threshold inserts are no-ops in ins10)
#pragma unroll
                for (int u = 0; u < 8; u++) {
                    bool p = dv[u] > thr;
                    if (__any_sync(0xffffffffu, p)) {
                        ins10(p ? dv[u] : NEGINF, base + j0 + u, dst, idx);
                    }
                }
                thr = dst[9];
            }
        }
    }

    // --- umbrella geometry on the 9 non-self neighbors (idx[1..9]) ---
    float vx[9], vy[9], vz[9], ph[9];
#pragma unroll
    for (int k = 0; k < 9; k++) {
        int j = idx[k+1];
        float ax = xb[j*3+0] - x0;
        float ay = xb[j*3+1] - x1;
        float az = xb[j*3+2] - x2;
        vx[k] = ax; vy[k] = ay; vz[k] = az;
        ph[k] = atan2f(ay, ax);   // monotone in reference phi -> same argsort order
    }
#pragma unroll
    for (int a = 0; a < 8; a++) {
#pragma unroll
        for (int c = 0; c < 8 - a; c++) {
            if (ph[c] > ph[c+1]) {
                float t;
                t = ph[c]; ph[c] = ph[c+1]; ph[c+1] = t;
                t = vx[c]; vx[c] = vx[c+1]; vx[c+1] = t;
                t = vy[c]; vy[c] = vy[c+1]; vy[c+1] = t;
                t = vz[c]; vz[c] = vz[c+1]; vz[c+1] = t;
            }
        }
    }
    float c0x = vy[0]*vz[1] - vz[0]*vy[1] + 1e-5f;
    const float mask = (c0x > 0.f) ? 1.f : -1.f;

    float lsum[7], lsq[7];
#pragma unroll
    for (int o = 0; o < 7; o++) { lsum[o] = 0.f; lsq[o] = 0.f; }

    const int bnkBase = (b * NN + n) * KNB;
#pragma unroll
    for (int k = 0; k < 9; k++) {
        const int k2 = (k + 1 == 9) ? 0 : k + 1;
        float ax = vx[k],  ay = vy[k],  az = vz[k];
        float bx = vx[k2], by = vy[k2], bz = vz[k2];
        float cx = 0.5f*(ax+bx), cy = 0.5f*(ay+by), cz = 0.5f*(az+bz);
        float ux = ay*bz - az*by + 1e-5f;
        float uy = az*bx - ax*bz + 1e-5f;
        float uz = ax*by - ay*bx + 1e-5f;
        float inv = rsqrtf(ux*ux + uy*uy + uz*uz) * mask;
        ux *= inv; uy *= inv; uz *= inv;
        float pos = (cx*ux + cy*uy + cz*uz) * 0.57735026918962576f;  // /sqrt(3)
        float f[7] = {cx, cy, cz, ux, uy, uz, pos};
#pragma unroll
        for (int o = 0; o < 7; o++) {
            float h = 0.f;
#pragma unroll
            for (int c = 0; c < 7; c++) h = fmaf(f[c], s_w1[o*7+c], h);
            g_feat[o*BNK + bnkBase + k] = h;
            lsum[o] += h;
            lsq[o]   = fmaf(h, h, lsq[o]);
        }
    }

    const int lane = tid & 31;
#pragma unroll
    for (int o = 0; o < 7; o++) {
        float s = lsum[o], q = lsq[o];
        for (int off = 16; off; off >>= 1) {
            s += __shfl_xor_sync(0xffffffffu, s, off);
            q += __shfl_xor_sync(0xffffffffu, q, off);
        }
        if (lane == 0) { atomicAdd(&s_acc[o], s); atomicAdd(&s_acc[7+o], q); }
    }
    __syncthreads();
    if (tid < 14) atomicAdd(&g_acc[tid], s_acc[tid]);
}

// ---------------------------------------------------------------------------
// K2: BN1 + relu + linear2(+bias2), accumulate BN2 stats (in-place on g_feat)
// ---------------------------------------------------------------------------
__global__ __launch_bounds__(256) void k_mlp2(const float* __restrict__ gamma1,
                                              const float* __restrict__ beta1,
                                              const float* __restrict__ w2,
                                              const float* __restrict__ bias2) {
    __shared__ float s_w2[49], s_b2[7], s_scale[7], s_shift[7], s_acc[14];
    const int tid = threadIdx.x;
    if (tid < 49) s_w2[tid] = w2[tid];
    if (tid < 7) {
        s_b2[tid] = bias2[tid];
        float m = g_acc[tid] * (1.f / BNK);
        float v = g_acc[7+tid] * (1.f / BNK) - m*m;
        float sc = gamma1[tid] * rsqrtf(v + BN_EPS);
        s_scale[tid] = sc;
        s_shift[tid] = beta1[tid] - m*sc;
    }
    if (tid < 14) s_acc[tid] = 0.f;
    __syncthreads();

    const int bnk = blockIdx.x * 256 + tid;
    float r[7];
#pragma unroll
    for (int c = 0; c < 7; c++) {
        float h = g_feat[c*BNK + bnk];
        h = fmaf(h, s_scale[c], s_shift[c]);
        r[c] = fmaxf(h, 0.f);
    }
    float h[7], lsq[7];
#pragma unroll
    for (int o = 0; o < 7; o++) {
        float hh = s_b2[o];
#pragma unroll
        for (int c = 0; c < 7; c++) hh = fmaf(r[c], s_w2[o*7+c], hh);
        g_feat[o*BNK + bnk] = hh;
        h[o] = hh;
        lsq[o] = hh * hh;
    }
    const int lane = tid & 31;
#pragma unroll
    for (int o = 0; o < 7; o++) {
        float s = h[o], q = lsq[o];
        for (int off = 16; off; off >>= 1) {
            s += __shfl_xor_sync(0xffffffffu, s, off);
            q += __shfl_xor_sync(0xffffffffu, q, off);
        }
        if (lane == 0) { atomicAdd(&s_acc[o], s); atomicAdd(&s_acc[7+o], q); }
    }
    __syncthreads();
    if (tid < 14) atomicAdd(&g_acc[14+tid], s_acc[tid]);
}

// ---------------------------------------------------------------------------
// K3: BN2 + relu + linear3(+bias3) + maxpool over K, concat with x -> out
// ---------------------------------------------------------------------------
__global__ __launch_bounds__(256) void k_mlp3(const float* __restrict__ x,
                                              const float* __restrict__ gamma2,
                                              const float* __restrict__ beta2,
                                              const float* __restrict__ w3,
                                              const float* __restrict__ bias3,
                                              float* __restrict__ out) {
    __shared__ float s_w3[49], s_b3[7], s_scale[7], s_shift[7];
    const int tid = threadIdx.x;
    if (tid < 49) s_w3[tid] = w3[tid];
    if (tid < 7) {
        s_b3[tid] = bias3[tid];
        float m = g_acc[14+tid] * (1.f / BNK);
        float v = g_acc[21+tid] * (1.f / BNK) - m*m;
        float sc = gamma2[tid] * rsqrtf(v + BN_EPS);
        s_scale[tid] = sc;
        s_shift[tid] = beta2[tid] - m*sc;
    }
    __syncthreads();

    const int bn = blockIdx.x * 256 + tid;   // 0 .. B*N-1
    float best[7];
#pragma unroll
    for (int o = 0; o < 7; o++) best[o] = NEGINF;

#pragma unroll
    for (int k = 0; k < 9; k++) {
        float r[7];
#pragma unroll
        for (int c = 0; c < 7; c++) {
            float h = g_feat[c*BNK + bn*KNB + k];
            h = fmaf(h, s_scale[c], s_shift[c]);
            r[c] = fmaxf(h, 0.f);
        }
#pragma unroll
        for (int o = 0; o < 7; o++) {
            float h = s_b3[o];
#pragma unroll
            for (int c = 0; c < 7; c++) h = fmaf(r[c], s_w3[o*7+c], h);
            best[o] = fmaxf(best[o], h);
        }
    }
    out[bn*10+0] = x[bn*3+0];
    out[bn*10+1] = x[bn*3+1];
    out[bn*10+2] = x[bn*3+2];
#pragma unroll
    for (int o = 0; o < 7; o++) out[bn*10+3+o] = best[o];
}

extern "C" void kernel_launch(void* const* d_in, const int* in_sizes, int n_in,
                              void* d_out, int out_size) {
    const float* x      = (const float*)d_in[0];
    const float* w1     = (const float*)d_in[1];
    const float* gamma1 = (const float*)d_in[2];
    const float* beta1  = (const float*)d_in[3];
    const float* w2     = (const float*)d_in[4];
    const float* bias2  = (const float*)d_in[5];
    const float* gamma2 = (const float*)d_in[6];
    const float* beta2  = (const float*)d_in[7];
    const float* w3     = (const float*)d_in[8];
    const float* bias3  = (const float*)d_in[9];
    float* out = (float*)d_out;

    k_zero<<<1, 32>>>();
    k_knn<<<BB * (NN / 128), 128>>>(x, w1);
    k_mlp2<<<BNK / 256, 256>>>(gamma1, beta1, w2, bias2);
    k_mlp3<<<(BB * NN) / 256, 256>>>(x, gamma2, beta2, w3, bias3, out);
}

// round 12
// speedup vs baseline: 1.4757x; 1.4757x over previous
#include <cuda_runtime.h>
#include <math.h>

#define BB 4
#define NN 8192
#define KNB 9
#define CH 7
#define BNK (BB*NN*KNB)
#define TILE 1024
#define BN_EPS 1e-5f
#define NEGINF (-3.4e38f)

// scratch (allocation-free): SoA feature buffer [channel][bnk] and BN accumulators
__device__ float g_feat[CH * BNK];
__device__ float g_acc[28];   // [0:7) sum1, [7:14) sumsq1, [14:21) sum2, [21:28) sumsq2

__global__ void k_zero() {
    int t = threadIdx.x;
    if (t < 28) g_acc[t] = 0.f;
}

// Parallel-select sorted insert (desc). Insert position = #{dst[k] >= d}:
// all predicates independent, outputs read only pre-insert state -> depth 2.
// Strict > keeps lower index on ties (ascending-j scan), matching jax.lax.top_k.
// d <= dst[9] (incl. NEGINF) is a guaranteed no-op.
__device__ __forceinline__ void ins10(float d, int j, float dst[10], int idx[10]) {
    bool p[10];
#pragma unroll
    for (int k = 0; k < 10; k++) p[k] = d > dst[k];
#pragma unroll
    for (int k = 9; k >= 1; k--) {
        dst[k] = p[k] ? (p[k-1] ? dst[k-1] : d) : dst[k];
        idx[k] = p[k] ? (p[k-1] ? idx[k-1] : j) : idx[k];
    }
    dst[0] = p[0] ? d : dst[0];
    idx[0] = p[0] ? j : idx[0];
}

// Merge-insert: same structure but tie-exact compound predicate so merging two
// half-scan lists reproduces jax.lax.top_k's lower-index-first tie order.
__device__ __forceinline__ void ins10m(float d, int j, float dst[10], int idx[10]) {
    bool p[10];
#pragma unroll
    for (int k = 0; k < 10; k++)
        p[k] = (d > dst[k]) || (d == dst[k] && j < idx[k]);
#pragma unroll
    for (int k = 9; k >= 1; k--) {
        dst[k] = p[k] ? (p[k-1] ? dst[k-1] : d) : dst[k];
        idx[k] = p[k] ? (p[k-1] ? idx[k-1] : j) : idx[k];
    }
    dst[0] = p[0] ? d : dst[0];
    idx[0] = p[0] ? j : idx[0];
}

// ---------------------------------------------------------------------------
// K1: brute-force top-10 (dist = 2*x.y - |x|^2 - |y|^2, desc) + umbrella
//     geometry + first 7x7 linear, accumulate BN1 stats.
//     2 threads per point scan disjoint tile halves; merged in-CTA.
//     256 CTAs x 256 thr -> 2 CTAs/SM co-resident -> ~4 warps/SMSP.
// ---------------------------------------------------------------------------
__global__ __launch_bounds__(256) void k_knn(const float* __restrict__ x,
                                             const float* __restrict__ w1) {
    __shared__ float4 tile[TILE];          // 16 KB; reused as merge buffer later
    __shared__ float s_w1[49];
    __shared__ float s_acc[14];

    const int tid  = threadIdx.x;
    const int half = tid >> 7;             // 0: scans j%1024 in [0,512), 1: [512,1024)
    const int pt   = tid & 127;
    const int b = blockIdx.x >> 6;         // 64 blocks per batch
    const int n = (blockIdx.x & 63) * 128 + pt;
    const float* xb = x + (size_t)b * NN * 3;

    if (tid < 49) s_w1[tid] = w1[tid];
    if (tid < 14) s_acc[tid] = 0.f;

    const float x0 = xb[n*3+0], x1 = xb[n*3+1], x2 = xb[n*3+2];
    const float xsqi = fmaf(x2, x2, fmaf(x1, x1, x0*x0));

    float dst[10]; int idx[10];
#pragma unroll
    for (int k = 0; k < 10; k++) { dst[k] = NEGINF; idx[k] = -1; }
    float thr = NEGINF;

    const int jlo = half * 512, jhi = jlo + 512;
    for (int base = 0; base < NN; base += TILE) {
        __syncthreads();
        for (int j = tid; j < TILE; j += 256) {
            float a  = xb[(base+j)*3+0];
            float c1 = xb[(base+j)*3+1];
            float c2 = xb[(base+j)*3+2];
            tile[j] = make_float4(a, c1, c2, fmaf(c2, c2, fmaf(c1, c1, a*a)));
        }
        __syncthreads();
        for (int j0 = jlo; j0 < jhi; j0 += 8) {
            float dv[8];
#pragma unroll
            for (int u = 0; u < 8; u++) {
                float4 s = tile[j0 + u];            // warp-uniform addr -> broadcast
                float t = x0 * s.x;
                t = fmaf(x1, s.y, t);
                t = fmaf(x2, s.z, t);
                dv[u] = fmaf(2.0f, t, -xsqi) - s.w; // same rounding as ref
            }
            // 8-wide pre-screen: one vote/branch per 8 candidates
            float m01 = fmaxf(dv[0], dv[1]), m23 = fmaxf(dv[2], dv[3]);
            float m45 = fmaxf(dv[4], dv[5]), m67 = fmaxf(dv[6], dv[7]);
            float m = fmaxf(fmaxf(m01, m23), fmaxf(m45, m67));
            if (__any_sync(0xffffffffu, m > thr)) {
#pragma unroll
                for (int u = 0; u < 8; u++) {
                    bool p = dv[u] > thr;
                    if (__any_sync(0xffffffffu, p)) {
                        ins10(p ? dv[u] : NEGINF, base + j0 + u, dst, idx);
                        thr = dst[9];
                    }
                }
            }
        }
    }

    // --- publish half-1 lists, merge into half-0 (tile is dead; overlay) ---
    __syncthreads();
    float* bufd = (float*)tile;            // [128][10] floats
    int*   bufi = (int*)(bufd + 1280);     // [128][10] ints
    if (half == 1) {
#pragma unroll
        for (int k = 0; k < 10; k++) {
            bufd[pt*10 + k] = dst[k];
            bufi[pt*10 + k] = idx[k];
        }
    }
    __syncthreads();

    if (half == 0) {
#pragma unroll
        for (int k = 0; k < 10; k++)
            ins10m(bufd[pt*10 + k], bufi[pt*10 + k], dst, idx);

        // --- umbrella geometry on the 9 non-self neighbors (idx[1..9]) ---
        float vx[9], vy[9], vz[9], ph[9];
#pragma unroll
        for (int k = 0; k < 9; k++) {
            int j = idx[k+1];
            float ax = xb[j*3+0] - x0;
            float ay = xb[j*3+1] - x1;
            float az = xb[j*3+2] - x2;
            vx[k] = ax; vy[k] = ay; vz[k] = az;
            ph[k] = atan2f(ay, ax);  // monotone in reference phi -> same argsort
        }
#pragma unroll
        for (int a = 0; a < 8; a++) {
#pragma unroll
            for (int c = 0; c < 8 - a; c++) {
                if (ph[c] > ph[c+1]) {
                    float t;
                    t = ph[c]; ph[c] = ph[c+1]; ph[c+1] = t;
                    t = vx[c]; vx[c] = vx[c+1]; vx[c+1] = t;
                    t = vy[c]; vy[c] = vy[c+1]; vy[c+1] = t;
                    t = vz[c]; vz[c] = vz[c+1]; vz[c+1] = t;
                }
            }
        }
        float c0x = vy[0]*vz[1] - vz[0]*vy[1] + 1e-5f;
        const float mask = (c0x > 0.f) ? 1.f : -1.f;

        float lsum[7], lsq[7];
#pragma unroll
        for (int o = 0; o < 7; o++) { lsum[o] = 0.f; lsq[o] = 0.f; }

        const int bnkBase = (b * NN + n) * KNB;
#pragma unroll
        for (int k = 0; k < 9; k++) {
            const int k2 = (k + 1 == 9) ? 0 : k + 1;
            float ax = vx[k],  ay = vy[k],  az = vz[k];
            float bx = vx[k2], by = vy[k2], bz = vz[k2];
            float cx = 0.5f*(ax+bx), cy = 0.5f*(ay+by), cz = 0.5f*(az+bz);
            float ux = ay*bz - az*by + 1e-5f;
            float uy = az*bx - ax*bz + 1e-5f;
            float uz = ax*by - ay*bx + 1e-5f;
            float inv = rsqrtf(ux*ux + uy*uy + uz*uz) * mask;
            ux *= inv; uy *= inv; uz *= inv;
            float pos = (cx*ux + cy*uy + cz*uz) * 0.57735026918962576f; // /sqrt(3)
            float f[7] = {cx, cy, cz, ux, uy, uz, pos};
#pragma unroll
            for (int o = 0; o < 7; o++) {
                float h = 0.f;
#pragma unroll
                for (int c = 0; c < 7; c++) h = fmaf(f[c], s_w1[o*7+c], h);
                g_feat[o*BNK + bnkBase + k] = h;
                lsum[o] += h;
                lsq[o]   = fmaf(h, h, lsq[o]);
            }
        }

        const int lane = tid & 31;
#pragma unroll
        for (int o = 0; o < 7; o++) {
            float s = lsum[o], q = lsq[o];
            for (int off = 16; off; off >>= 1) {
                s += __shfl_xor_sync(0xffffffffu, s, off);
                q += __shfl_xor_sync(0xffffffffu, q, off);
            }
            if (lane == 0) { atomicAdd(&s_acc[o], s); atomicAdd(&s_acc[7+o], q); }
        }
    }
    __syncthreads();
    if (tid < 14) atomicAdd(&g_acc[tid], s_acc[tid]);
}

// ---------------------------------------------------------------------------
// K2: BN1 + relu + linear2(+bias2), accumulate BN2 stats (in-place on g_feat)
// ---------------------------------------------------------------------------
__global__ __launch_bounds__(256) void k_mlp2(const float* __restrict__ gamma1,
                                              const float* __restrict__ beta1,
                                              const float* __restrict__ w2,
                                              const float* __restrict__ bias2) {
    __shared__ float s_w2[49], s_b2[7], s_scale[7], s_shift[7], s_acc[14];
    const int tid = threadIdx.x;
    if (tid < 49) s_w2[tid] = w2[tid];
    if (tid < 7) {
        s_b2[tid] = bias2[tid];
        float m = g_acc[tid] * (1.f / BNK);
        float v = g_acc[7+tid] * (1.f / BNK) - m*m;
        float sc = gamma1[tid] * rsqrtf(v + BN_EPS);
        s_scale[tid] = sc;
        s_shift[tid] = beta1[tid] - m*sc;
    }
    if (tid < 14) s_acc[tid] = 0.f;
    __syncthreads();

    const int bnk = blockIdx.x * 256 + tid;
    float r[7];
#pragma unroll
    for (int c = 0; c < 7; c++) {
        float h = g_feat[c*BNK + bnk];
        h = fmaf(h, s_scale[c], s_shift[c]);
        r[c] = fmaxf(h, 0.f);
    }
    float h[7], lsq[7];
#pragma unroll
    for (int o = 0; o < 7; o++) {
        float hh = s_b2[o];
#pragma unroll
        for (int c = 0; c < 7; c++) hh = fmaf(r[c], s_w2[o*7+c], hh);
        g_feat[o*BNK + bnk] = hh;
        h[o] = hh;
        lsq[o] = hh * hh;
    }
    const int lane = tid & 31;
#pragma unroll
    for (int o = 0; o < 7; o++) {
        float s = h[o], q = lsq[o];
        for (int off = 16; off; off >>= 1) {
            s += __shfl_xor_sync(0xffffffffu, s, off);
            q += __shfl_xor_sync(0xffffffffu, q, off);
        }
        if (lane == 0) { atomicAdd(&s_acc[o], s); atomicAdd(&s_acc[7+o], q); }
    }
    __syncthreads();
    if (tid < 14) atomicAdd(&g_acc[14+tid], s_acc[tid]);
}

// ---------------------------------------------------------------------------
// K3: BN2 + relu + linear3(+bias3) + maxpool over K, concat with x -> out
// ---------------------------------------------------------------------------
__global__ __launch_bounds__(256) void k_mlp3(const float* __restrict__ x,
                                              const float* __restrict__ gamma2,
                                              const float* __restrict__ beta2,
                                              const float* __restrict__ w3,
                                              const float* __restrict__ bias3,
                                              float* __restrict__ out) {
    __shared__ float s_w3[49], s_b3[7], s_scale[7], s_shift[7];
    const int tid = threadIdx.x;
    if (tid < 49) s_w3[tid] = w3[tid];
    if (tid < 7) {
        s_b3[tid] = bias3[tid];
        float m = g_acc[14+tid] * (1.f / BNK);
        float v = g_acc[21+tid] * (1.f / BNK) - m*m;
        float sc = gamma2[tid] * rsqrtf(v + BN_EPS);
        s_scale[tid] = sc;
        s_shift[tid] = beta2[tid] - m*sc;
    }
    __syncthreads();

    const int bn = blockIdx.x * 256 + tid;   // 0 .. B*N-1
    float best[7];
#pragma unroll
    for (int o = 0; o < 7; o++) best[o] = NEGINF;

#pragma unroll
    for (int k = 0; k < 9; k++) {
        float r[7];
#pragma unroll
        for (int c = 0; c < 7; c++) {
            float h = g_feat[c*BNK + bn*KNB + k];
            h = fmaf(h, s_scale[c], s_shift[c]);
            r[c] = fmaxf(h, 0.f);
        }
#pragma unroll
        for (int o = 0; o < 7; o++) {
            float h = s_b3[o];
#pragma unroll
            for (int c = 0; c < 7; c++) h = fmaf(r[c], s_w3[o*7+c], h);
            best[o] = fmaxf(best[o], h);
        }
    }
    out[bn*10+0] = x[bn*3+0];
    out[bn*10+1] = x[bn*3+1];
    out[bn*10+2] = x[bn*3+2];
#pragma unroll
    for (int o = 0; o < 7; o++) out[bn*10+3+o] = best[o];
}

extern "C" void kernel_launch(void* const* d_in, const int* in_sizes, int n_in,
                              void* d_out, int out_size) {
    const float* x      = (const float*)d_in[0];
    const float* w1     = (const float*)d_in[1];
    const float* gamma1 = (const float*)d_in[2];
    const float* beta1  = (const float*)d_in[3];
    const float* w2     = (const float*)d_in[4];
    const float* bias2  = (const float*)d_in[5];
    const float* gamma2 = (const float*)d_in[6];
    const float* beta2  = (const float*)d_in[7];
    const float* w3     = (const float*)d_in[8];
    const float* bias3  = (const float*)d_in[9];
    float* out = (float*)d_out;

    k_zero<<<1, 32>>>();
    k_knn<<<BB * 64, 256>>>(x, w1);
    k_mlp2<<<BNK / 256, 256>>>(gamma1, beta1, w2, bias2);
    k_mlp3<<<(BB * NN) / 256, 256>>>(x, gamma2, beta2, w3, bias3, out);
}

// round 13
// speedup vs baseline: 1.5278x; 1.0353x over previous
#include <cuda_runtime.h>
#include <math.h>

#define BB 4
#define NN 8192
#define KNB 9
#define CH 7
#define BNK (BB*NN*KNB)
#define TILE 1024
#define BN_EPS 1e-5f
#define NEGINF (-3.4e38f)

// scratch (allocation-free): SoA feature buffer [channel][bnk] and BN accumulators
__device__ float g_feat[CH * BNK];
__device__ float g_acc[28];   // [0:7) sum1, [7:14) sumsq1, [14:21) sum2, [21:28) sumsq2

__global__ void k_zero() {
    int t = threadIdx.x;
    if (t < 28) g_acc[t] = 0.f;
}

// Parallel-select sorted insert (desc). Insert position = #{dst[k] >= d}:
// all predicates independent, outputs read only pre-insert state -> depth 2.
// Strict > keeps lower index on ties (ascending-j scan), matching jax.lax.top_k.
// d <= dst[9] (incl. NEGINF) is a guaranteed no-op.
__device__ __forceinline__ void ins10(float d, int j, float dst[10], int idx[10]) {
    bool p[10];
#pragma unroll
    for (int k = 0; k < 10; k++) p[k] = d > dst[k];
#pragma unroll
    for (int k = 9; k >= 1; k--) {
        dst[k] = p[k] ? (p[k-1] ? dst[k-1] : d) : dst[k];
        idx[k] = p[k] ? (p[k-1] ? idx[k-1] : j) : idx[k];
    }
    dst[0] = p[0] ? d : dst[0];
    idx[0] = p[0] ? j : idx[0];
}

// ---------------------------------------------------------------------------
// K1: brute-force top-10 (dist = 2*x.y - |x|^2 - |y|^2, desc) + umbrella
//     geometry + first 7x7 linear, accumulate BN1 stats.
//     R8 config: 128 CTAs x 256 threads, full-8192 scan per thread.
//     Triggered-block interior rebuilt: stale-thr predicates + one REDUX.OR,
//     no per-candidate FSETP->VOTE->BRA chains.
// ---------------------------------------------------------------------------
__global__ __launch_bounds__(256) void k_knn(const float* __restrict__ x,
                                             const float* __restrict__ w1) {
    __shared__ float4 tile[TILE];
    __shared__ float s_w1[49];
    __shared__ float s_acc[14];

    const int tid = threadIdx.x;
    const int b = blockIdx.x >> 5;                 // 32 blocks per batch
    const int n = (blockIdx.x & 31) * 256 + tid;
    const float* xb = x + (size_t)b * NN * 3;

    if (tid < 49) s_w1[tid] = w1[tid];
    if (tid < 14) s_acc[tid] = 0.f;

    const float x0 = xb[n*3+0], x1 = xb[n*3+1], x2 = xb[n*3+2];
    const float xsqi = fmaf(x2, x2, fmaf(x1, x1, x0*x0));

    float dst[10]; int idx[10];
#pragma unroll
    for (int k = 0; k < 10; k++) { dst[k] = NEGINF; idx[k] = -1; }
    float thr = NEGINF;

    for (int base = 0; base < NN; base += TILE) {
        __syncthreads();
        for (int j = tid; j < TILE; j += 256) {
            float a  = xb[(base+j)*3+0];
            float c1 = xb[(base+j)*3+1];
            float c2 = xb[(base+j)*3+2];
            tile[j] = make_float4(a, c1, c2, fmaf(c2, c2, fmaf(c1, c1, a*a)));
        }
        __syncthreads();
        for (int j0 = 0; j0 < TILE; j0 += 8) {
            float dv[8];
#pragma unroll
            for (int u = 0; u < 8; u++) {
                float4 s = tile[j0 + u];            // uniform addr -> smem broadcast
                float t = x0 * s.x;
                t = fmaf(x1, s.y, t);
                t = fmaf(x2, s.z, t);
                dv[u] = fmaf(2.0f, t, -xsqi) - s.w; // same rounding as ref
            }
            // cheap pre-screen: one vote/branch per 8 candidates
            float m01 = fmaxf(dv[0], dv[1]), m23 = fmaxf(dv[2], dv[3]);
            float m45 = fmaxf(dv[4], dv[5]), m67 = fmaxf(dv[6], dv[7]);
            float m = fmaxf(fmaxf(m01, m23), fmaxf(m45, m67));
            if (__any_sync(0xffffffffu, m > thr)) {
                // stale-thr predicates (independent, pipelined). Inserts of
                // d <= live dst[9] are no-ops in ins10 -> bit-exact.
                unsigned pb = 0u;
#pragma unroll
                for (int u = 0; u < 8; u++)
                    pb |= dv[u] > thr ? (1u << u) : 0u;
                // one warp reduction replaces 8 votes; anyb is warp-uniform
                unsigned anyb = __reduce_or_sync(0xffffffffu, pb);
#pragma unroll
                for (int u = 0; u < 8; u++) {
                    if (anyb & (1u << u)) {         // uniform branch, no vote
                        ins10((pb >> u) & 1u ? dv[u] : NEGINF,
                              base + j0 + u, dst, idx);
                    }
                }
                thr = dst[9];
            }
        }
    }

    // --- umbrella geometry on the 9 non-self neighbors (idx[1..9]) ---
    float vx[9], vy[9], vz[9], ph[9];
#pragma unroll
    for (int k = 0; k < 9; k++) {
        int j = idx[k+1];
        float ax = xb[j*3+0] - x0;
        float ay = xb[j*3+1] - x1;
        float az = xb[j*3+2] - x2;
        vx[k] = ax; vy[k] = ay; vz[k] = az;
        ph[k] = atan2f(ay, ax);   // monotone in reference phi -> same argsort order
    }
#pragma unroll
    for (int a = 0; a < 8; a++) {
#pragma unroll
        for (int c = 0; c < 8 - a; c++) {
            if (ph[c] > ph[c+1]) {
                float t;
                t = ph[c]; ph[c] = ph[c+1]; ph[c+1] = t;
                t = vx[c]; vx[c] = vx[c+1]; vx[c+1] = t;
                t = vy[c]; vy[c] = vy[c+1]; vy[c+1] = t;
                t = vz[c]; vz[c] = vz[c+1]; vz[c+1] = t;
            }
        }
    }
    float c0x = vy[0]*vz[1] - vz[0]*vy[1] + 1e-5f;
    const float mask = (c0x > 0.f) ? 1.f : -1.f;

    float lsum[7], lsq[7];
#pragma unroll
    for (int o = 0; o < 7; o++) { lsum[o] = 0.f; lsq[o] = 0.f; }

    const int bnkBase = (b * NN + n) * KNB;
#pragma unroll
    for (int k = 0; k < 9; k++) {
        const int k2 = (k + 1 == 9) ? 0 : k + 1;
        float ax = vx[k],  ay = vy[k],  az = vz[k];
        float bx = vx[k2], by = vy[k2], bz = vz[k2];
        float cx = 0.5f*(ax+bx), cy = 0.5f*(ay+by), cz = 0.5f*(az+bz);
        float ux = ay*bz - az*by + 1e-5f;
        float uy = az*bx - ax*bz + 1e-5f;
        float uz = ax*by - ay*bx + 1e-5f;
        float inv = rsqrtf(ux*ux + uy*uy + uz*uz) * mask;
        ux *= inv; uy *= inv; uz *= inv;
        float pos = (cx*ux + cy*uy + cz*uz) * 0.57735026918962576f;  // /sqrt(3)
        float f[7] = {cx, cy, cz, ux, uy, uz, pos};
#pragma unroll
        for (int o = 0; o < 7; o++) {
            float h = 0.f;
#pragma unroll
            for (int c = 0; c < 7; c++) h = fmaf(f[c], s_w1[o*7+c], h);
            g_feat[o*BNK + bnkBase + k] = h;
            lsum[o] += h;
            lsq[o]   = fmaf(h, h, lsq[o]);
        }
    }

    const int lane = tid & 31;
#pragma unroll
    for (int o = 0; o < 7; o++) {
        float s = lsum[o], q = lsq[o];
        for (int off = 16; off; off >>= 1) {
            s += __shfl_xor_sync(0xffffffffu, s, off);
            q += __shfl_xor_sync(0xffffffffu, q, off);
        }
        if (lane == 0) { atomicAdd(&s_acc[o], s); atomicAdd(&s_acc[7+o], q); }
    }
    __syncthreads();
    if (tid < 14) atomicAdd(&g_acc[tid], s_acc[tid]);
}

// ---------------------------------------------------------------------------
// K2: BN1 + relu + linear2(+bias2), accumulate BN2 stats (in-place on g_feat)
// ---------------------------------------------------------------------------
__global__ __launch_bounds__(256) void k_mlp2(const float* __restrict__ gamma1,
                                              const float* __restrict__ beta1,
                                              const float* __restrict__ w2,
                                              const float* __restrict__ bias2) {
    __shared__ float s_w2[49], s_b2[7], s_scale[7], s_shift[7], s_acc[14];
    const int tid = threadIdx.x;
    if (tid < 49) s_w2[tid] = w2[tid];
    if (tid < 7) {
        s_b2[tid] = bias2[tid];
        float m = g_acc[tid] * (1.f / BNK);
        float v = g_acc[7+tid] * (1.f / BNK) - m*m;
        float sc = gamma1[tid] * rsqrtf(v + BN_EPS);
        s_scale[tid] = sc;
        s_shift[tid] = beta1[tid] - m*sc;
    }
    if (tid < 14) s_acc[tid] = 0.f;
    __syncthreads();

    const int bnk = blockIdx.x * 256 + tid;
    float r[7];
#pragma unroll
    for (int c = 0; c < 7; c++) {
        float h = g_feat[c*BNK + bnk];
        h = fmaf(h, s_scale[c], s_shift[c]);
        r[c] = fmaxf(h, 0.f);
    }
    float h[7], lsq[7];
#pragma unroll
    for (int o = 0; o < 7; o++) {
        float hh = s_b2[o];
#pragma unroll
        for (int c = 0; c < 7; c++) hh = fmaf(r[c], s_w2[o*7+c], hh);
        g_feat[o*BNK + bnk] = hh;
        h[o] = hh;
        lsq[o] = hh * hh;
    }
    const int lane = tid & 31;
#pragma unroll
    for (int o = 0; o < 7; o++) {
        float s = h[o], q = lsq[o];
        for (int off = 16; off; off >>= 1) {
            s += __shfl_xor_sync(0xffffffffu, s, off);
            q += __shfl_xor_sync(0xffffffffu, q, off);
        }
        if (lane == 0) { atomicAdd(&s_acc[o], s); atomicAdd(&s_acc[7+o], q); }
    }
    __syncthreads();
    if (tid < 14) atomicAdd(&g_acc[14+tid], s_acc[tid]);
}

// ---------------------------------------------------------------------------
// K3: BN2 + relu + linear3(+bias3) + maxpool over K, concat with x -> out
// ---------------------------------------------------------------------------
__global__ __launch_bounds__(256) void k_mlp3(const float* __restrict__ x,
                                              const float* __restrict__ gamma2,
                                              const float* __restrict__ beta2,
                                              const float* __restrict__ w3,
                                              const float* __restrict__ bias3,
                                              float* __restrict__ out) {
    __shared__ float s_w3[49], s_b3[7], s_scale[7], s_shift[7];
    const int tid = threadIdx.x;
    if (tid < 49) s_w3[tid] = w3[tid];
    if (tid < 7) {
        s_b3[tid] = bias3[tid];
        float m = g_acc[14+tid] * (1.f / BNK);
        float v = g_acc[21+tid] * (1.f / BNK) - m*m;
        float sc = gamma2[tid] * rsqrtf(v + BN_EPS);
        s_scale[tid] = sc;
        s_shift[tid] = beta2[tid] - m*sc;
    }
    __syncthreads();

    const int bn = blockIdx.x * 256 + tid;   // 0 .. B*N-1
    float best[7];
#pragma unroll
    for (int o = 0; o < 7; o++) best[o] = NEGINF;

#pragma unroll
    for (int k = 0; k < 9; k++) {
        float r[7];
#pragma unroll
        for (int c = 0; c < 7; c++) {
            float h = g_feat[c*BNK + bn*KNB + k];
            h = fmaf(h, s_scale[c], s_shift[c]);
            r[c] = fmaxf(h, 0.f);
        }
#pragma unroll
        for (int o = 0; o < 7; o++) {
            float h = s_b3[o];
#pragma unroll
            for (int c = 0; c < 7; c++) h = fmaf(r[c], s_w3[o*7+c], h);
            best[o] = fmaxf(best[o], h);
        }
    }
    out[bn*10+0] = x[bn*3+0];
    out[bn*10+1] = x[bn*3+1];
    out[bn*10+2] = x[bn*3+2];
#pragma unroll
    for (int o = 0; o < 7; o++) out[bn*10+3+o] = best[o];
}

extern "C" void kernel_launch(void* const* d_in, const int* in_sizes, int n_in,
                              void* d_out, int out_size) {
    const float* x      = (const float*)d_in[0];
    const float* w1     = (const float*)d_in[1];
    const float* gamma1 = (const float*)d_in[2];
    const float* beta1  = (const float*)d_in[3];
    const float* w2     = (const float*)d_in[4];
    const float* bias2  = (const float*)d_in[5];
    const float* gamma2 = (const float*)d_in[6];
    const float* beta2  = (const float*)d_in[7];
    const float* w3     = (const float*)d_in[8];
    const float* bias3  = (const float*)d_in[9];
    float* out = (float*)d_out;

    k_zero<<<1, 32>>>();
    k_knn<<<BB * (NN / 256), 256>>>(x, w1);
    k_mlp2<<<BNK / 256, 256>>>(gamma1, beta1, w2, bias2);
    k_mlp3<<<(BB * NN) / 256, 256>>>(x, gamma2, beta2, w3, bias3, out);
}